// round 9
// baseline (speedup 1.0000x reference)
#include <cuda_runtime.h>
#include <cstdint>

#define SEQ   8192
#define DIM   128
#define GATES 512
#define TOK_PER_BLK 8
#define ROWS_PER_CTA 256
#define LSTM_THREADS 256
#define ARRIVES 64

typedef unsigned long long u64;

// Scratch (device globals; no runtime allocation allowed)
__device__ float g_z[SEQ * DIM];        // expert-linear output, 4 MB
__device__ float g_xg[SEQ * GATES];     // precomputed input-gate contributions, 16 MB

// ---------------------------------------------------------------------------
// f32x2 packed helpers (FFMA2 only reachable via PTX fma.rn.f32x2)
// ---------------------------------------------------------------------------
__device__ __forceinline__ u64 fma2(u64 a, u64 b, u64 c) {
    u64 d;
    asm("fma.rn.f32x2 %0, %1, %2, %3;" : "=l"(d) : "l"(a), "l"(b), "l"(c));
    return d;
}
__device__ __forceinline__ u64 add2(u64 a, u64 b) {
    u64 d;
    asm("add.rn.f32x2 %0, %1, %2;" : "=l"(d) : "l"(a), "l"(b));
    return d;
}
__device__ __forceinline__ u64 pack2(float lo, float hi) {
    u64 p;
    asm("mov.b64 %0, {%1, %2};" : "=l"(p) : "r"(__float_as_uint(lo)), "r"(__float_as_uint(hi)));
    return p;
}
__device__ __forceinline__ float hsum2(u64 p) {
    unsigned int lo, hi;
    asm("mov.b64 {%0, %1}, %2;" : "=r"(lo), "=r"(hi) : "l"(p));
    return __uint_as_float(lo) + __uint_as_float(hi);
}

__device__ __forceinline__ float fast_sigmoid(float x) {
    return 1.0f / (1.0f + __expf(-x));
}
__device__ __forceinline__ float fast_tanh(float x) {
    // exact at saturation: exp(2x)->inf gives 1, ->0 gives -1
    return 1.0f - 2.0f / (__expf(2.0f * x) + 1.0f);
}

// ---------------------------------------------------------------------------
// Cluster / mbarrier primitives
// ---------------------------------------------------------------------------
__device__ __forceinline__ uint32_t smem_u32(const void* p) {
    uint32_t a;
    asm("{ .reg .u64 t; cvta.to.shared.u64 t, %1; cvt.u32.u64 %0, t; }"
        : "=r"(a) : "l"(p));
    return a;
}
__device__ __forceinline__ uint32_t ctarank() {
    uint32_t r;
    asm("mov.u32 %0, %%cluster_ctarank;" : "=r"(r));
    return r;
}
__device__ __forceinline__ uint32_t mapa_u32(uint32_t addr, uint32_t rank) {
    uint32_t r;
    asm("mapa.shared::cluster.u32 %0, %1, %2;" : "=r"(r) : "r"(addr), "r"(rank));
    return r;
}
__device__ __forceinline__ void st_cluster_v4(uint32_t addr, float4 v) {
    asm volatile("st.shared::cluster.v4.b32 [%0], {%1, %2, %3, %4};"
                 :: "r"(addr),
                    "r"(__float_as_uint(v.x)), "r"(__float_as_uint(v.y)),
                    "r"(__float_as_uint(v.z)), "r"(__float_as_uint(v.w)) : "memory");
}
__device__ __forceinline__ void mbar_init(uint32_t bar, uint32_t cnt) {
    asm volatile("mbarrier.init.shared.b64 [%0], %1;" :: "r"(bar), "r"(cnt) : "memory");
}
// release.cluster: orders THIS thread's preceding st.shared::cluster before the arrival
__device__ __forceinline__ void mbar_arrive_release_cluster(uint32_t bar) {
    asm volatile("mbarrier.arrive.release.cluster.shared::cluster.b64 _, [%0];"
                 :: "r"(bar) : "memory");
}
__device__ __forceinline__ void mbar_wait_parity_cluster(uint32_t bar, uint32_t parity) {
    uint32_t done;
    do {
        asm volatile(
            "{\n\t.reg .pred p;\n\t"
            "mbarrier.try_wait.parity.acquire.cluster.shared::cta.b64 p, [%1], %2;\n\t"
            "selp.b32 %0, 1, 0, p;\n\t}"
            : "=r"(done) : "r"(bar), "r"(parity) : "memory");
    } while (!done);
}
__device__ __forceinline__ void cluster_sync() {
    asm volatile("barrier.cluster.arrive.aligned;" ::: "memory");
    asm volatile("barrier.cluster.wait.aligned;" ::: "memory");
}

// ---------------------------------------------------------------------------
// Phase A: z[s,i] = sum_j W_exp[e(s),i,j]*embs[s,j] + b_exp[e(s),i]
// ---------------------------------------------------------------------------
__global__ void k_expert(const float* __restrict__ embs,
                         const int* __restrict__ pos_ids,
                         const float* __restrict__ W_exp,
                         const float* __restrict__ b_exp) {
    __shared__ float e_s[DIM];
    int s = blockIdx.x;
    int i = threadIdx.x;
    e_s[i] = embs[s * DIM + i];
    __syncthreads();
    int e = pos_ids[s];
    const float* Wr = W_exp + ((size_t)e * DIM + i) * DIM;
    float acc = b_exp[e * DIM + i];
#pragma unroll
    for (int q = 0; q < DIM / 4; q++) {
        float4 w4 = *reinterpret_cast<const float4*>(Wr + 4 * q);
        acc = fmaf(w4.x, e_s[4 * q + 0], acc);
        acc = fmaf(w4.y, e_s[4 * q + 1], acc);
        acc = fmaf(w4.z, e_s[4 * q + 2], acc);
        acc = fmaf(w4.w, e_s[4 * q + 3], acc);
    }
    g_z[s * DIM + i] = acc;
}

// ---------------------------------------------------------------------------
// Phase B: xg[s,t] = sum_j z[s,j]*W_ih[t,j] + b_ih[t] + b_hh[t]
// ---------------------------------------------------------------------------
__global__ void k_inproj(const float* __restrict__ W_ih,
                         const float* __restrict__ b_ih,
                         const float* __restrict__ b_hh) {
    __shared__ float z_s[TOK_PER_BLK][DIM];
    int t = threadIdx.x;
    int tok0 = blockIdx.x * TOK_PER_BLK;
    for (int i = t; i < TOK_PER_BLK * DIM; i += GATES)
        z_s[i / DIM][i % DIM] = g_z[tok0 * DIM + i];
    __syncthreads();
    float acc[TOK_PER_BLK];
    float b = b_ih[t] + b_hh[t];
#pragma unroll
    for (int r = 0; r < TOK_PER_BLK; r++) acc[r] = b;
    const float* Wr = W_ih + t * DIM;
#pragma unroll
    for (int q = 0; q < DIM / 4; q++) {
        float4 w4 = *reinterpret_cast<const float4*>(Wr + 4 * q);
#pragma unroll
        for (int r = 0; r < TOK_PER_BLK; r++) {
            acc[r] = fmaf(w4.x, z_s[r][4 * q + 0], acc[r]);
            acc[r] = fmaf(w4.y, z_s[r][4 * q + 1], acc[r]);
            acc[r] = fmaf(w4.z, z_s[r][4 * q + 2], acc[r]);
            acc[r] = fmaf(w4.w, z_s[r][4 * q + 3], acc[r]);
        }
    }
#pragma unroll
    for (int r = 0; r < TOK_PER_BLK; r++)
        g_xg[(size_t)(tok0 + r) * GATES + t] = acc[r];
}

// ---------------------------------------------------------------------------
// Phase C+D: LSTM scan on a 2-CTA cluster. CTA rank r owns gate rows
// [256r, 256r+256): one full W_hh row per thread, fully register-resident.
// Per step:
//   GEMV -> activation -> local gate store -> __syncthreads ->
//   threads 0..63 each: LDS.128 staged gates + st.shared::cluster.v4 (16B)
//   to peer + OWN release-arrive on peer's mbarrier (count=64) ->
//   all threads: acquire-wait own mbarrier -> (local+peer gates visible,
//   no extra barrier) c/h update redundantly in both CTAs -> __syncthreads.
// ---------------------------------------------------------------------------
__global__ __cluster_dims__(2, 1, 1) __launch_bounds__(LSTM_THREADS, 1)
void k_lstm2(const float* __restrict__ W_hh, float* __restrict__ out) {
    __shared__ __align__(16) u64 h2[DIM / 2];          // h as 64 f32x2 pairs
    __shared__ __align__(16) float gate_s[2][GATES];   // double-buffered gates
    __shared__ __align__(8) u64 mbar;
    float* h_f = (float*)h2;

    int t = threadIdx.x;
    uint32_t rank = ctarank();
    uint32_t peer = rank ^ 1u;
    int row = (int)rank * ROWS_PER_CTA + t;
    bool is_g = (rank == 1) && (t < DIM);   // rows 256..383 = g gate (tanh)

    // W_hh row fully in registers
    u64 w2[64];
    const u64* Wr = reinterpret_cast<const u64*>(W_hh + (size_t)row * DIM);
#pragma unroll
    for (int j = 0; j < 64; j++) w2[j] = Wr[j];

    uint32_t bar = smem_u32(&mbar);
    if (t == 0) mbar_init(bar, ARRIVES);   // 64 vector-store arrivals from peer
    if (t < DIM) h_f[t] = 0.0f;
    __syncthreads();
    cluster_sync();   // both CTAs' barriers initialized before any remote arrive

    // remote addresses: peer's barrier; peer's copy of MY row block, per buffer
    uint32_t rbar = mapa_u32(bar, peer);
    uint32_t my_blk0 = smem_u32(&gate_s[0][rank * ROWS_PER_CTA]);
    uint32_t my_blk1 = smem_u32(&gate_s[1][rank * ROWS_PER_CTA]);
    uint32_t rg0 = mapa_u32(my_blk0, peer) + (uint32_t)t * 16u;
    uint32_t rg1 = mapa_u32(my_blk1, peer) + (uint32_t)t * 16u;

    float c = 0.0f;
    float hmax = -3.0e38f;
    float xg_next = g_xg[row];   // step 0's input contribution

    for (int step = 0; step < SEQ; step++) {
        int buf = step & 1;
        u64 a0 = pack2(xg_next, 0.0f);
        u64 a1 = pack2(0.0f, 0.0f);
        u64 a2 = a1, a3 = a1;
        int nstep = min(step + 1, SEQ - 1);
        xg_next = __ldg(&g_xg[(size_t)nstep * GATES + row]);

        const ulonglong2* hh = reinterpret_cast<const ulonglong2*>(h2);
#pragma unroll
        for (int q = 0; q < 16; q++) {
            ulonglong2 p0 = hh[2 * q];       // broadcast LDS
            ulonglong2 p1 = hh[2 * q + 1];
            a0 = fma2(w2[4 * q + 0], p0.x, a0);
            a1 = fma2(w2[4 * q + 1], p0.y, a1);
            a2 = fma2(w2[4 * q + 2], p1.x, a2);
            a3 = fma2(w2[4 * q + 3], p1.y, a3);
        }
        float v = hsum2(add2(add2(a0, a1), add2(a2, a3)));
        float gv = is_g ? fast_tanh(v) : fast_sigmoid(v);

        gate_s[buf][row] = gv;               // local copy (stage for exchange)
        __syncthreads();                     // all 256 local gates staged

        if (t < ARRIVES) {
            // ship 4 gates per thread to peer; own release-arrive orders them
            float4 g4 = *reinterpret_cast<const float4*>(
                &gate_s[buf][rank * ROWS_PER_CTA + t * 4]);
            st_cluster_v4(buf ? rg1 : rg0, g4);
            mbar_arrive_release_cluster(rbar);
        }

        mbar_wait_parity_cluster(bar, step & 1);   // acquire: peer gates visible

        if (t < DIM) {
            float iv = gate_s[buf][t];
            float fv = gate_s[buf][DIM + t];
            float gg = gate_s[buf][2 * DIM + t];
            float ov = gate_s[buf][3 * DIM + t];
            c = fmaf(fv, c, iv * gg);
            float h = ov * fast_tanh(c);
            hmax = fmaxf(hmax, h);
            h_f[t] = h;                      // redundant in both CTAs
        }
        __syncthreads();                     // h visible before next GEMV
    }

    if (rank == 0 && t < DIM) out[t] = hmax;
    cluster_sync();   // keep peer smem alive until all remote ops drained
}

// ---------------------------------------------------------------------------
extern "C" void kernel_launch(void* const* d_in, const int* in_sizes, int n_in,
                              void* d_out, int out_size) {
    const float* embs  = (const float*)d_in[0];
    const int*   pos   = (const int*)  d_in[1];
    const float* W_exp = (const float*)d_in[2];
    const float* b_exp = (const float*)d_in[3];
    const float* W_ih  = (const float*)d_in[4];
    const float* W_hh  = (const float*)d_in[5];
    const float* b_ih  = (const float*)d_in[6];
    const float* b_hh  = (const float*)d_in[7];
    float* out = (float*)d_out;

    k_expert<<<SEQ, DIM>>>(embs, pos, W_exp, b_exp);
    k_inproj<<<SEQ / TOK_PER_BLK, GATES>>>(W_ih, b_ih, b_hh);
    k_lstm2<<<2, LSTM_THREADS>>>(W_hh, out);
}